// round 1
// baseline (speedup 1.0000x reference)
#include <cuda_runtime.h>
#include <math.h>

#define BATCH 16
#define NSEQ  1024
#define NH    8
#define HD    64
#define DM    512
#define MROWS (BATCH*NSEQ)   // 16384

// ---------------- scratch (static device arrays; no allocation) ----------------
__device__ float g_q[BATCH*NH*NSEQ*HD];     // [b,h,n,d]
__device__ float g_k[BATCH*NH*NSEQ*HD];
__device__ float g_v[BATCH*NH*NSEQ*HD];
__device__ float g_attn[BATCH*NSEQ*DM];     // [b,n, h*64+d]

// =============================================================================
// GEMM: C[M,512] = X[M,512] @ W[512,512] + bias
// BM=128, BN=64, BK=16, 256 threads, 8x4 per-thread tile.
// MODE 0: scatter output to [b,h,n,d] layout.  MODE 1: plain row-major.
// =============================================================================
template<int MODE>
__global__ __launch_bounds__(256) void gemm512(
    const float* __restrict__ X, const float* __restrict__ W,
    const float* __restrict__ bias, float* __restrict__ out)
{
    __shared__ float As[16][132];   // transposed A tile (k-major)
    __shared__ float Bs[16][64];

    const int tid = threadIdx.x;
    const int tx  = tid & 15;       // 16 col-threads * 4 = 64 cols
    const int ty  = tid >> 4;       // 16 row-threads * 8 = 128 rows
    const int rowBase = blockIdx.y * 128;
    const int colBase = blockIdx.x * 64;

    float acc[8][4];
    #pragma unroll
    for (int i = 0; i < 8; i++)
        #pragma unroll
        for (int j = 0; j < 4; j++) acc[i][j] = 0.f;

    for (int kt = 0; kt < 512; kt += 16) {
        // A tile: 128x16 = 512 float4, 2 per thread, stored transposed
        #pragma unroll
        for (int i = 0; i < 2; i++) {
            int v = tid + i * 256;
            int r = v >> 2, cv = (v & 3) * 4;
            float4 a = *(const float4*)&X[(size_t)(rowBase + r) * 512 + kt + cv];
            As[cv + 0][r] = a.x; As[cv + 1][r] = a.y;
            As[cv + 2][r] = a.z; As[cv + 3][r] = a.w;
        }
        // B tile: 16x64 = 256 float4, 1 per thread
        {
            int r = tid >> 4, cv = (tid & 15) * 4;
            *(float4*)&Bs[r][cv] = *(const float4*)&W[(size_t)(kt + r) * 512 + colBase + cv];
        }
        __syncthreads();

        #pragma unroll
        for (int k = 0; k < 16; k++) {
            float af[8], bf[4];
            *(float4*)&af[0] = *(float4*)&As[k][ty * 8];
            *(float4*)&af[4] = *(float4*)&As[k][ty * 8 + 4];
            *(float4*)&bf[0] = *(float4*)&Bs[k][tx * 4];
            #pragma unroll
            for (int i = 0; i < 8; i++)
                #pragma unroll
                for (int j = 0; j < 4; j++)
                    acc[i][j] += af[i] * bf[j];
        }
        __syncthreads();
    }

    #pragma unroll
    for (int i = 0; i < 8; i++) {
        int m = rowBase + ty * 8 + i;
        #pragma unroll
        for (int j = 0; j < 4; j++) {
            int c = colBase + tx * 4 + j;
            float val = acc[i][j] + bias[c];
            if (MODE == 0) {
                int bi = m >> 10, ni = m & 1023;
                int h  = c >> 6,  d  = c & 63;
                out[(size_t)(((bi * NH + h) << 10) + ni) * 64 + d] = val;
            } else {
                out[(size_t)m * 512 + c] = val;
            }
        }
    }
}

// =============================================================================
// Fused attention: per block = one (b,h,32-row q tile).
//  - scores S[32][1024] live entirely in SMEM
//  - S = QK^T/8 + log(max(w,1e-6)); softmax; write mn once; O = P @ V
// =============================================================================
#define QT 32
#define CK 128
// smem layout (floats): sS[32][1032] | sKV[128*68 union(Kt[64][132], V[128][68])] | sQt[64][36]
#define SS_STRIDE 1032
#define OFF_KV   (QT * SS_STRIDE)          // 33024
#define OFF_QT   (OFF_KV + 128 * 68)       // 41728
#define SMEM_FLOATS (OFF_QT + 64 * 36)     // 44032
#define SMEM_BYTES (SMEM_FLOATS * 4)       // 176128

__global__ __launch_bounds__(256, 1) void attn_kernel(
    const float* __restrict__ gq, const float* __restrict__ gk,
    const float* __restrict__ gv, const float* __restrict__ gw,
    float* __restrict__ mn, float* __restrict__ attnout)
{
    extern __shared__ float smem[];
    float* sS  = smem;
    float* sKV = smem + OFF_KV;   // Kt[d*132+col] during QK, V[k*68+d] during AV
    float* sQt = smem + OFF_QT;   // Qt[d*36+row], pre-scaled by 1/8

    const int tid = threadIdx.x;
    const int q0  = blockIdx.x * QT;
    const int hh  = blockIdx.y;
    const int bb  = blockIdx.z;
    const size_t bhBase = (size_t)(bb * NH + hh) * NSEQ;   // row base into [b,h,n,*]

    // ---- load Q tile, transposed, pre-scaled by 1/sqrt(64) ----
    #pragma unroll
    for (int i = 0; i < 2; i++) {
        int v = tid + i * 256;
        int r = v >> 4, d4 = (v & 15) * 4;
        float4 f = *(const float4*)&gq[(bhBase + q0 + r) * 64 + d4];
        sQt[(d4 + 0) * 36 + r] = f.x * 0.125f;
        sQt[(d4 + 1) * 36 + r] = f.y * 0.125f;
        sQt[(d4 + 2) * 36 + r] = f.z * 0.125f;
        sQt[(d4 + 3) * 36 + r] = f.w * 0.125f;
    }

    // ---- QK^T + log-bias, chunked over K ----
    const int tx = tid & 15;   // cols tx*8 .. tx*8+7
    const int ty = tid >> 4;   // rows ty, ty+16

    for (int kb = 0; kb < NSEQ; kb += CK) {
        // load K chunk transposed: Kt[d][col]
        #pragma unroll
        for (int i = 0; i < 8; i++) {
            int v = tid + i * 256;
            int col = v >> 4, d4 = (v & 15) * 4;
            float4 f = *(const float4*)&gk[(bhBase + kb + col) * 64 + d4];
            sKV[(d4 + 0) * 132 + col] = f.x;
            sKV[(d4 + 1) * 132 + col] = f.y;
            sKV[(d4 + 2) * 132 + col] = f.z;
            sKV[(d4 + 3) * 132 + col] = f.w;
        }
        __syncthreads();

        float s0[8], s1[8];
        #pragma unroll
        for (int j = 0; j < 8; j++) { s0[j] = 0.f; s1[j] = 0.f; }

        #pragma unroll 8
        for (int d = 0; d < 64; d++) {
            float qa = sQt[d * 36 + ty];
            float qb = sQt[d * 36 + ty + 16];
            float kf[8];
            *(float4*)&kf[0] = *(float4*)&sKV[d * 132 + tx * 8];
            *(float4*)&kf[4] = *(float4*)&sKV[d * 132 + tx * 8 + 4];
            #pragma unroll
            for (int j = 0; j < 8; j++) {
                s0[j] += qa * kf[j];
                s1[j] += qb * kf[j];
            }
        }

        // add log(max(w,1e-6)) and store to sS
        #pragma unroll
        for (int ir = 0; ir < 2; ir++) {
            int r = ty + ir * 16;
            float* s = ir ? s1 : s0;
            const float* wrow = gw + ((bhBase + q0 + r) << 10) + kb + tx * 8;
            float4 w0 = *(const float4*)&wrow[0];
            float4 w1 = *(const float4*)&wrow[4];
            s[0] += __logf(fmaxf(w0.x, 1e-6f));
            s[1] += __logf(fmaxf(w0.y, 1e-6f));
            s[2] += __logf(fmaxf(w0.z, 1e-6f));
            s[3] += __logf(fmaxf(w0.w, 1e-6f));
            s[4] += __logf(fmaxf(w1.x, 1e-6f));
            s[5] += __logf(fmaxf(w1.y, 1e-6f));
            s[6] += __logf(fmaxf(w1.z, 1e-6f));
            s[7] += __logf(fmaxf(w1.w, 1e-6f));
            *(float4*)&sS[r * SS_STRIDE + kb + tx * 8]     = make_float4(s[0], s[1], s[2], s[3]);
            *(float4*)&sS[r * SS_STRIDE + kb + tx * 8 + 4] = make_float4(s[4], s[5], s[6], s[7]);
        }
        __syncthreads();
    }

    // ---- softmax per row (warp per row, 4 rows/warp), write mn ----
    {
        const int warp = tid >> 5, lane = tid & 31;
        #pragma unroll
        for (int rr = 0; rr < 4; rr++) {
            int r = warp + rr * 8;
            float* row = sS + r * SS_STRIDE;
            float m = -1e30f;
            #pragma unroll
            for (int i = 0; i < 8; i++) {
                float4 f = *(float4*)&row[(lane + i * 32) * 4];
                m = fmaxf(m, fmaxf(fmaxf(f.x, f.y), fmaxf(f.z, f.w)));
            }
            #pragma unroll
            for (int o = 16; o; o >>= 1) m = fmaxf(m, __shfl_xor_sync(0xffffffffu, m, o));

            float sum = 0.f;
            #pragma unroll
            for (int i = 0; i < 8; i++) {
                float4 f = *(float4*)&row[(lane + i * 32) * 4];
                f.x = __expf(f.x - m); f.y = __expf(f.y - m);
                f.z = __expf(f.z - m); f.w = __expf(f.w - m);
                sum += (f.x + f.y) + (f.z + f.w);
                *(float4*)&row[(lane + i * 32) * 4] = f;
            }
            #pragma unroll
            for (int o = 16; o; o >>= 1) sum += __shfl_xor_sync(0xffffffffu, sum, o);
            float inv = 1.f / sum;

            float* mrow = mn + ((bhBase + q0 + r) << 10);
            #pragma unroll
            for (int i = 0; i < 8; i++) {
                float4 f = *(float4*)&row[(lane + i * 32) * 4];
                f.x *= inv; f.y *= inv; f.z *= inv; f.w *= inv;
                *(float4*)&row[(lane + i * 32) * 4]  = f;
                *(float4*)&mrow[(lane + i * 32) * 4] = f;
            }
        }
    }
    __syncthreads();

    // ---- O = P @ V, chunked over K; V reuses the KV smem buffer ----
    float o[8];
    #pragma unroll
    for (int j = 0; j < 8; j++) o[j] = 0.f;
    const int r2 = tid >> 3;         // 32 rows
    const int dg = tid & 7;          // 8 d-groups * 8 = 64

    for (int kb = 0; kb < NSEQ; kb += CK) {
        #pragma unroll
        for (int i = 0; i < 8; i++) {
            int v = tid + i * 256;
            int k = v >> 4, d4 = (v & 15) * 4;
            *(float4*)&sKV[k * 68 + d4] =
                *(const float4*)&gv[(bhBase + kb + k) * 64 + d4];
        }
        __syncthreads();

        const float* prow = sS + r2 * SS_STRIDE + kb;
        #pragma unroll 8
        for (int k = 0; k < CK; k++) {
            float p = prow[k];
            float vf[8];
            *(float4*)&vf[0] = *(float4*)&sKV[k * 68 + dg * 8];
            *(float4*)&vf[4] = *(float4*)&sKV[k * 68 + dg * 8 + 4];
            #pragma unroll
            for (int j = 0; j < 8; j++) o[j] += p * vf[j];
        }
        __syncthreads();
    }

    // write attn scratch [b, n, h*64+d]
    {
        float* dst = attnout + (size_t)(bb * NSEQ + q0 + r2) * DM + hh * 64 + dg * 8;
        *(float4*)&dst[0] = make_float4(o[0], o[1], o[2], o[3]);
        *(float4*)&dst[4] = make_float4(o[4], o[5], o[6], o[7]);
    }
}

// =============================================================================
extern "C" void kernel_launch(void* const* d_in, const int* in_sizes, int n_in,
                              void* d_out, int out_size)
{
    const float* queries = (const float*)d_in[0];
    const float* keys    = (const float*)d_in[1];
    const float* values  = (const float*)d_in[2];
    const float* relw    = (const float*)d_in[3];
    const float* Wq = (const float*)d_in[4];
    const float* bq = (const float*)d_in[5];
    const float* Wk = (const float*)d_in[6];
    const float* bk = (const float*)d_in[7];
    const float* Wv = (const float*)d_in[8];
    const float* bv = (const float*)d_in[9];
    const float* Wo = (const float*)d_in[10];
    const float* bo = (const float*)d_in[11];

    float* out_main = (float*)d_out;                        // [16,1024,512]
    float* out_mn   = (float*)d_out + (size_t)BATCH * NSEQ * DM;  // [b*h,1024,1024]

    float *gq, *gk, *gv, *gattn;
    cudaGetSymbolAddress((void**)&gq, g_q);
    cudaGetSymbolAddress((void**)&gk, g_k);
    cudaGetSymbolAddress((void**)&gv, g_v);
    cudaGetSymbolAddress((void**)&gattn, g_attn);

    dim3 ggrid(8, 128);   // 512/64 cols, 16384/128 rows

    gemm512<0><<<ggrid, 256>>>(queries, Wq, bq, gq);
    gemm512<0><<<ggrid, 256>>>(keys,    Wk, bk, gk);
    gemm512<0><<<ggrid, 256>>>(values,  Wv, bv, gv);

    cudaFuncSetAttribute(attn_kernel,
                         cudaFuncAttributeMaxDynamicSharedMemorySize, SMEM_BYTES);
    attn_kernel<<<dim3(NSEQ / QT, NH, BATCH), 256, SMEM_BYTES>>>(
        gq, gk, gv, relw, out_mn, gattn);

    gemm512<1><<<ggrid, 256>>>(gattn, Wo, bo, out_main);
}

// round 3
// speedup vs baseline: 1.1250x; 1.1250x over previous
#include <cuda_runtime.h>
#include <cuda_bf16.h>
#include <cstdint>
#include <math.h>

#define BATCH 16
#define NSEQ  1024
#define NH    8
#define HD    64
#define DM    512

// ---------------- scratch (static device arrays; no allocation) ----------------
__device__ float g_q[BATCH*NH*NSEQ*HD];     // [b,h,n,d]
__device__ float g_k[BATCH*NH*NSEQ*HD];
__device__ float g_v[BATCH*NH*NSEQ*HD];
__device__ float g_attn[BATCH*NSEQ*DM];     // [b,n, h*64+d]

// =============================================================================
// helpers
// =============================================================================
__device__ __forceinline__ uint32_t smem_u32(const void* p) {
    uint32_t a;
    asm("{ .reg .u64 t; cvta.to.shared.u64 t, %1; cvt.u32.u64 %0, t; }"
        : "=r"(a) : "l"(p));
    return a;
}

__device__ __forceinline__ void ldsm_x4(uint32_t* r, uint32_t addr) {
    asm volatile("ldmatrix.sync.aligned.m8n8.x4.shared.b16 {%0,%1,%2,%3}, [%4];"
        : "=r"(r[0]), "=r"(r[1]), "=r"(r[2]), "=r"(r[3]) : "r"(addr));
}
__device__ __forceinline__ void ldsm_x4t(uint32_t* r, uint32_t addr) {
    asm volatile("ldmatrix.sync.aligned.m8n8.x4.trans.shared.b16 {%0,%1,%2,%3}, [%4];"
        : "=r"(r[0]), "=r"(r[1]), "=r"(r[2]), "=r"(r[3]) : "r"(addr));
}
__device__ __forceinline__ void mma_bf16(float* c, const uint32_t* a,
                                         uint32_t b0, uint32_t b1) {
    asm volatile(
        "mma.sync.aligned.m16n8k16.row.col.f32.bf16.bf16.f32 "
        "{%0,%1,%2,%3}, {%4,%5,%6,%7}, {%8,%9}, {%0,%1,%2,%3};"
        : "+f"(c[0]), "+f"(c[1]), "+f"(c[2]), "+f"(c[3])
        : "r"(a[0]), "r"(a[1]), "r"(a[2]), "r"(a[3]), "r"(b0), "r"(b1));
}

__device__ __forceinline__ uint32_t pack_bf16_res(float a, float b, float& ra, float& rb) {
    __nv_bfloat16 ha = __float2bfloat16(a), hb = __float2bfloat16(b);
    ra = a - __bfloat162float(ha);
    rb = b - __bfloat162float(hb);
    __nv_bfloat162 p(ha, hb);
    return *reinterpret_cast<uint32_t*>(&p);
}
__device__ __forceinline__ uint32_t pack_bf16(float a, float b) {
    __nv_bfloat162 p(__float2bfloat16(a), __float2bfloat16(b));
    return *reinterpret_cast<uint32_t*>(&p);
}

// =============================================================================
// Tensor-core (HMMA mma.sync) GEMM: C[16384,512] = X @ W + bias
// bf16 split-3 (hi*hi + hi*lo + lo*hi), fp32 accumulate -> ~1.5e-5 element err.
// CTA: 128x128 tile, BK=32, 256 threads (8 warps, 2x4 grid, 64x32 warp tile).
// Double-buffered SMEM. MODE 0: scatter to [b,h,n,d]. MODE 1: row-major.
// =============================================================================
#define ASTRIDE 40            // bf16 elems per A row (32 + 8 pad)
#define BSTRIDE 136           // bf16 elems per B row (128 + 8 pad)
#define A_BYTES (128*ASTRIDE*2)   // 10240
#define B_BYTES (32*BSTRIDE*2)    // 8704
#define OFF_ALO A_BYTES
#define OFF_BHI (2*A_BYTES)
#define OFF_BLO (2*A_BYTES + B_BYTES)
#define GBUF    (2*A_BYTES + 2*B_BYTES)   // 37888
#define GEMM_SMEM (2*GBUF)                // 75776

template<int MODE>
__global__ __launch_bounds__(256, 1) void gemm_tc(
    const float* __restrict__ X, const float* __restrict__ W,
    const float* __restrict__ bias, float* __restrict__ out)
{
    extern __shared__ char smem[];
    const uint32_t sb = smem_u32(smem);
    const int tid  = threadIdx.x;
    const int wid  = tid >> 5, lane = tid & 31;
    const int wm   = wid >> 2;          // 0..1  (64-row slab)
    const int wn   = wid & 3;           // 0..3  (32-col slab)
    const int n0   = blockIdx.x * 128;
    const int m0   = blockIdx.y * 128;

    float acc[4][4][4];                 // [m16 tile][n8 tile][frag]
    #pragma unroll
    for (int i = 0; i < 4; i++)
        #pragma unroll
        for (int j = 0; j < 4; j++)
            #pragma unroll
            for (int k = 0; k < 4; k++) acc[i][j][k] = 0.f;

    float4 ra[4], rb[4];

    // ---- global load of chunk c into regs ----
    auto gload = [&](int c) {
        const int k0 = c * 32;
        #pragma unroll
        for (int i = 0; i < 4; i++) {
            int idx = i * 256 + tid;
            int row = idx >> 3, col = (idx & 7) * 4;
            ra[i] = *(const float4*)&X[(size_t)(m0 + row) * 512 + k0 + col];
        }
        #pragma unroll
        for (int i = 0; i < 4; i++) {
            int idx = i * 256 + tid;
            int kk = idx >> 5, col = (idx & 31) * 4;
            rb[i] = *(const float4*)&W[(size_t)(k0 + kk) * 512 + n0 + col];
        }
    };

    // ---- convert + store regs into smem buffer ----
    auto cstore = [&](int buf) {
        char* bp = smem + buf * GBUF;
        #pragma unroll
        for (int i = 0; i < 4; i++) {
            int idx = i * 256 + tid;
            int row = idx >> 3, col = (idx & 7) * 4;
            float r0, r1, r2, r3;
            uint2 hi, lo;
            hi.x = pack_bf16_res(ra[i].x, ra[i].y, r0, r1);
            hi.y = pack_bf16_res(ra[i].z, ra[i].w, r2, r3);
            lo.x = pack_bf16(r0, r1);
            lo.y = pack_bf16(r2, r3);
            uint32_t off = (uint32_t)(row * ASTRIDE + col) * 2;
            *(uint2*)(bp + off)          = hi;
            *(uint2*)(bp + OFF_ALO + off) = lo;
        }
        #pragma unroll
        for (int i = 0; i < 4; i++) {
            int idx = i * 256 + tid;
            int kk = idx >> 5, col = (idx & 31) * 4;
            float r0, r1, r2, r3;
            uint2 hi, lo;
            hi.x = pack_bf16_res(rb[i].x, rb[i].y, r0, r1);
            hi.y = pack_bf16_res(rb[i].z, rb[i].w, r2, r3);
            lo.x = pack_bf16(r0, r1);
            lo.y = pack_bf16(r2, r3);
            uint32_t off = (uint32_t)(kk * BSTRIDE + col) * 2;
            *(uint2*)(bp + OFF_BHI + off) = hi;
            *(uint2*)(bp + OFF_BLO + off) = lo;
        }
    };

    // ldmatrix lane-address components
    const uint32_t aLane = (uint32_t)((wm * 64 + (lane & 15)) * ASTRIDE + (lane >> 4) * 8) * 2;
    const uint32_t bLane = (uint32_t)((lane & 15) * BSTRIDE + wn * 32 + (lane >> 4) * 8) * 2;

    auto compute = [&](int buf) {
        const uint32_t base = sb + buf * GBUF;
        #pragma unroll
        for (int ks = 0; ks < 2; ks++) {
            uint32_t ah[4][4], al[4][4], bh[2][4], bl[2][4];
            #pragma unroll
            for (int mt = 0; mt < 4; mt++) {
                uint32_t ad = base + aLane + (uint32_t)(mt * 16 * ASTRIDE + ks * 16) * 2;
                ldsm_x4(ah[mt], ad);
                ldsm_x4(al[mt], ad + OFF_ALO);
            }
            #pragma unroll
            for (int nt = 0; nt < 2; nt++) {
                uint32_t bd = base + OFF_BHI + bLane +
                              (uint32_t)(ks * 16 * BSTRIDE + nt * 16) * 2;
                ldsm_x4t(bh[nt], bd);
                ldsm_x4t(bl[nt], bd + B_BYTES);
            }
            #pragma unroll
            for (int mt = 0; mt < 4; mt++) {
                #pragma unroll
                for (int n8 = 0; n8 < 4; n8++) {
                    const int nt = n8 >> 1, hf = (n8 & 1) * 2;
                    float* c = acc[mt][n8];
                    mma_bf16(c, ah[mt], bh[nt][hf], bh[nt][hf + 1]);
                    mma_bf16(c, ah[mt], bl[nt][hf], bl[nt][hf + 1]);
                    mma_bf16(c, al[mt], bh[nt][hf], bh[nt][hf + 1]);
                }
            }
        }
    };

    // ---- pipeline over 16 K-chunks ----
    gload(0);
    cstore(0);
    __syncthreads();
    for (int c = 0; c < 16; c++) {
        if (c < 15) gload(c + 1);
        compute(c & 1);
        if (c < 15) {
            cstore((c + 1) & 1);
            __syncthreads();
        }
    }

    // ---- epilogue: bias + store ----
    const int gid = lane >> 2;          // 0..7
    const int cid = (lane & 3) * 2;     // 0,2,4,6
    #pragma unroll
    for (int mt = 0; mt < 4; mt++) {
        #pragma unroll
        for (int n8 = 0; n8 < 4; n8++) {
            int row = m0 + wm * 64 + mt * 16 + gid;
            int col = n0 + wn * 32 + n8 * 8 + cid;
            float b0 = __ldg(&bias[col]), b1 = __ldg(&bias[col + 1]);
            float2 v0 = make_float2(acc[mt][n8][0] + b0, acc[mt][n8][1] + b1);
            float2 v1 = make_float2(acc[mt][n8][2] + b0, acc[mt][n8][3] + b1);
            if (MODE == 0) {
                int h = col >> 6, d = col & 63;
                int bi0 = row >> 10, ni0 = row & 1023;
                *(float2*)&out[(size_t)(((bi0 * NH + h) << 10) + ni0) * 64 + d] = v0;
                int r1i = row + 8;
                int bi1 = r1i >> 10, ni1 = r1i & 1023;
                *(float2*)&out[(size_t)(((bi1 * NH + h) << 10) + ni1) * 64 + d] = v1;
            } else {
                *(float2*)&out[(size_t)row * 512 + col]       = v0;
                *(float2*)&out[(size_t)(row + 8) * 512 + col] = v1;
            }
        }
    }
}

// =============================================================================
// Fused attention (unchanged from R1): per block = one (b,h,32-row q tile).
// =============================================================================
#define QT 32
#define CK 128
#define SS_STRIDE 1032
#define OFF_KV   (QT * SS_STRIDE)
#define OFF_QT   (OFF_KV + 128 * 68)
#define SMEM_FLOATS (OFF_QT + 64 * 36)
#define SMEM_BYTES (SMEM_FLOATS * 4)

__global__ __launch_bounds__(256, 1) void attn_kernel(
    const float* __restrict__ gq, const float* __restrict__ gk,
    const float* __restrict__ gv, const float* __restrict__ gw,
    float* __restrict__ mn, float* __restrict__ attnout)
{
    extern __shared__ float smemf[];
    float* sS  = smemf;
    float* sKV = smemf + OFF_KV;
    float* sQt = smemf + OFF_QT;

    const int tid = threadIdx.x;
    const int q0  = blockIdx.x * QT;
    const int hh  = blockIdx.y;
    const int bb  = blockIdx.z;
    const size_t bhBase = (size_t)(bb * NH + hh) * NSEQ;

    #pragma unroll
    for (int i = 0; i < 2; i++) {
        int v = tid + i * 256;
        int r = v >> 4, d4 = (v & 15) * 4;
        float4 f = *(const float4*)&gq[(bhBase + q0 + r) * 64 + d4];
        sQt[(d4 + 0) * 36 + r] = f.x * 0.125f;
        sQt[(d4 + 1) * 36 + r] = f.y * 0.125f;
        sQt[(d4 + 2) * 36 + r] = f.z * 0.125f;
        sQt[(d4 + 3) * 36 + r] = f.w * 0.125f;
    }

    const int tx = tid & 15;
    const int ty = tid >> 4;

    for (int kb = 0; kb < NSEQ; kb += CK) {
        #pragma unroll
        for (int i = 0; i < 8; i++) {
            int v = tid + i * 256;
            int col = v >> 4, d4 = (v & 15) * 4;
            float4 f = *(const float4*)&gk[(bhBase + kb + col) * 64 + d4];
            sKV[(d4 + 0) * 132 + col] = f.x;
            sKV[(d4 + 1) * 132 + col] = f.y;
            sKV[(d4 + 2) * 132 + col] = f.z;
            sKV[(d4 + 3) * 132 + col] = f.w;
        }
        __syncthreads();

        float s0[8], s1[8];
        #pragma unroll
        for (int j = 0; j < 8; j++) { s0[j] = 0.f; s1[j] = 0.f; }

        #pragma unroll 8
        for (int d = 0; d < 64; d++) {
            float qa = sQt[d * 36 + ty];
            float qb = sQt[d * 36 + ty + 16];
            float kf[8];
            *(float4*)&kf[0] = *(float4*)&sKV[d * 132 + tx * 8];
            *(float4*)&kf[4] = *(float4*)&sKV[d * 132 + tx * 8 + 4];
            #pragma unroll
            for (int j = 0; j < 8; j++) {
                s0[j] += qa * kf[j];
                s1[j] += qb * kf[j];
            }
        }

        #pragma unroll
        for (int ir = 0; ir < 2; ir++) {
            int r = ty + ir * 16;
            float* s = ir ? s1 : s0;
            const float* wrow = gw + ((bhBase + q0 + r) << 10) + kb + tx * 8;
            float4 w0 = *(const float4*)&wrow[0];
            float4 w1 = *(const float4*)&wrow[4];
            s[0] += __logf(fmaxf(w0.x, 1e-6f));
            s[1] += __logf(fmaxf(w0.y, 1e-6f));
            s[2] += __logf(fmaxf(w0.z, 1e-6f));
            s[3] += __logf(fmaxf(w0.w, 1e-6f));
            s[4] += __logf(fmaxf(w1.x, 1e-6f));
            s[5] += __logf(fmaxf(w1.y, 1e-6f));
            s[6] += __logf(fmaxf(w1.z, 1e-6f));
            s[7] += __logf(fmaxf(w1.w, 1e-6f));
            *(float4*)&sS[r * SS_STRIDE + kb + tx * 8]     = make_float4(s[0], s[1], s[2], s[3]);
            *(float4*)&sS[r * SS_STRIDE + kb + tx * 8 + 4] = make_float4(s[4], s[5], s[6], s[7]);
        }
        __syncthreads();
    }

    {
        const int warp = tid >> 5, lane = tid & 31;
        #pragma unroll
        for (int rr = 0; rr < 4; rr++) {
            int r = warp + rr * 8;
            float* row = sS + r * SS_STRIDE;
            float m = -1e30f;
            #pragma unroll
            for (int i = 0; i < 8; i++) {
                float4 f = *(float4*)&row[(lane + i * 32) * 4];
                m = fmaxf(m, fmaxf(fmaxf(f.x, f.y), fmaxf(f.z, f.w)));
            }
            #pragma unroll
            for (int o = 16; o; o >>= 1) m = fmaxf(m, __shfl_xor_sync(0xffffffffu, m, o));

            float sum = 0.f;
            #pragma unroll
            for (int i = 0; i < 8; i++) {
                float4 f = *(float4*)&row[(lane + i * 32) * 4];
                f.x = __expf(f.x - m); f.y = __expf(f.y - m);
                f.z = __expf(f.z - m); f.w = __expf(f.w - m);
                sum += (f.x + f.y) + (f.z + f.w);
                *(float4*)&row[(lane + i * 32) * 4] = f;
            }
            #pragma unroll
            for (int o = 16; o; o >>= 1) sum += __shfl_xor_sync(0xffffffffu, sum, o);
            float inv = 1.f / sum;

            float* mrow = mn + ((bhBase + q0 + r) << 10);
            #pragma unroll
            for (int i = 0; i < 8; i++) {
                float4 f = *(float4*)&row[(lane + i * 32) * 4];
                f.x *= inv; f.y *= inv; f.z *= inv; f.w *= inv;
                *(float4*)&row[(lane + i * 32) * 4]  = f;
                *(float4*)&mrow[(lane + i * 32) * 4] = f;
            }
        }
    }
    __syncthreads();

    float o[8];
    #pragma unroll
    for (int j = 0; j < 8; j++) o[j] = 0.f;
    const int r2 = tid >> 3;
    const int dg = tid & 7;

    for (int kb = 0; kb < NSEQ; kb += CK) {
        #pragma unroll
        for (int i = 0; i < 8; i++) {
            int v = tid + i * 256;
            int k = v >> 4, d4 = (v & 15) * 4;
            *(float4*)&sKV[k * 68 + d4] =
                *(const float4*)&gv[(bhBase + kb + k) * 64 + d4];
        }
        __syncthreads();

        const float* prow = sS + r2 * SS_STRIDE + kb;
        #pragma unroll 8
        for (int k = 0; k < CK; k++) {
            float p = prow[k];
            float vf[8];
            *(float4*)&vf[0] = *(float4*)&sKV[k * 68 + dg * 8];
            *(float4*)&vf[4] = *(float4*)&sKV[k * 68 + dg * 8 + 4];
            #pragma unroll
            for (int j = 0; j < 8; j++) o[j] += p * vf[j];
        }
        __syncthreads();
    }

    {
        float* dst = attnout + (size_t)(bb * NSEQ + q0 + r2) * DM + hh * 64 + dg * 8;
        *(float4*)&dst[0] = make_float4(o[0], o[1], o[2], o[3]);
        *(float4*)&dst[4] = make_float4(o[4], o[5], o[6], o[7]);
    }
}

// =============================================================================
extern "C" void kernel_launch(void* const* d_in, const int* in_sizes, int n_in,
                              void* d_out, int out_size)
{
    const float* queries = (const float*)d_in[0];
    const float* keys    = (const float*)d_in[1];
    const float* values  = (const float*)d_in[2];
    const float* relw    = (const float*)d_in[3];
    const float* Wq = (const float*)d_in[4];
    const float* bq = (const float*)d_in[5];
    const float* Wk = (const float*)d_in[6];
    const float* bk = (const float*)d_in[7];
    const float* Wv = (const float*)d_in[8];
    const float* bv = (const float*)d_in[9];
    const float* Wo = (const float*)d_in[10];
    const float* bo = (const float*)d_in[11];

    float* out_main = (float*)d_out;
    float* out_mn   = (float*)d_out + (size_t)BATCH * NSEQ * DM;

    float *gq, *gk, *gv, *gattn;
    cudaGetSymbolAddress((void**)&gq, g_q);
    cudaGetSymbolAddress((void**)&gk, g_k);
    cudaGetSymbolAddress((void**)&gv, g_v);
    cudaGetSymbolAddress((void**)&gattn, g_attn);

    cudaFuncSetAttribute(gemm_tc<0>, cudaFuncAttributeMaxDynamicSharedMemorySize, GEMM_SMEM);
    cudaFuncSetAttribute(gemm_tc<1>, cudaFuncAttributeMaxDynamicSharedMemorySize, GEMM_SMEM);
    cudaFuncSetAttribute(attn_kernel, cudaFuncAttributeMaxDynamicSharedMemorySize, SMEM_BYTES);

    dim3 ggrid(4, 128);   // 512/128 n-tiles, 16384/128 m-tiles

    gemm_tc<0><<<ggrid, 256, GEMM_SMEM>>>(queries, Wq, bq, gq);
    gemm_tc<0><<<ggrid, 256, GEMM_SMEM>>>(keys,    Wk, bk, gk);
    gemm_tc<0><<<ggrid, 256, GEMM_SMEM>>>(values,  Wv, bv, gv);

    attn_kernel<<<dim3(NSEQ / QT, NH, BATCH), 256, SMEM_BYTES>>>(
        gq, gk, gv, relw, out_mn, gattn);

    gemm_tc<1><<<ggrid, 256, GEMM_SMEM>>>(gattn, Wo, bo, out_main);
}

// round 4
// speedup vs baseline: 4.1218x; 3.6637x over previous
#include <cuda_runtime.h>
#include <cuda_bf16.h>
#include <cstdint>
#include <math.h>

#define BATCH 16
#define NSEQ  1024
#define NH    8
#define HD    64
#define DM    512

// ---------------- scratch (static device arrays; no allocation) ----------------
#define QKV_ELEMS (BATCH*NH*NSEQ*HD)   // 8388608
__device__ __nv_bfloat16 g_qhi[QKV_ELEMS];
__device__ __nv_bfloat16 g_qlo[QKV_ELEMS];
__device__ __nv_bfloat16 g_khi[QKV_ELEMS];
__device__ __nv_bfloat16 g_klo[QKV_ELEMS];
__device__ __nv_bfloat16 g_vhi[QKV_ELEMS];
__device__ __nv_bfloat16 g_vlo[QKV_ELEMS];
__device__ float g_attn[BATCH*NSEQ*DM];     // [b,n, h*64+d]

// =============================================================================
// helpers
// =============================================================================
__device__ __forceinline__ uint32_t smem_u32(const void* p) {
    uint32_t a;
    asm("{ .reg .u64 t; cvta.to.shared.u64 t, %1; cvt.u32.u64 %0, t; }"
        : "=r"(a) : "l"(p));
    return a;
}
__device__ __forceinline__ void ldsm_x4(uint32_t* r, uint32_t addr) {
    asm volatile("ldmatrix.sync.aligned.m8n8.x4.shared.b16 {%0,%1,%2,%3}, [%4];"
        : "=r"(r[0]), "=r"(r[1]), "=r"(r[2]), "=r"(r[3]) : "r"(addr));
}
__device__ __forceinline__ void ldsm_x4t(uint32_t* r, uint32_t addr) {
    asm volatile("ldmatrix.sync.aligned.m8n8.x4.trans.shared.b16 {%0,%1,%2,%3}, [%4];"
        : "=r"(r[0]), "=r"(r[1]), "=r"(r[2]), "=r"(r[3]) : "r"(addr));
}
__device__ __forceinline__ void mma_bf16(float* c, const uint32_t* a,
                                         uint32_t b0, uint32_t b1) {
    asm volatile(
        "mma.sync.aligned.m16n8k16.row.col.f32.bf16.bf16.f32 "
        "{%0,%1,%2,%3}, {%4,%5,%6,%7}, {%8,%9}, {%0,%1,%2,%3};"
        : "+f"(c[0]), "+f"(c[1]), "+f"(c[2]), "+f"(c[3])
        : "r"(a[0]), "r"(a[1]), "r"(a[2]), "r"(a[3]), "r"(b0), "r"(b1));
}
__device__ __forceinline__ void cp16(uint32_t dst, const void* src) {
    asm volatile("cp.async.cg.shared.global [%0], [%1], 16;" :: "r"(dst), "l"(src));
}
#define CP_COMMIT() asm volatile("cp.async.commit_group;" ::: "memory")
#define CP_WAIT0()  asm volatile("cp.async.wait_group 0;" ::: "memory")

__device__ __forceinline__ uint32_t pack_bf16_res(float a, float b, float& ra, float& rb) {
    __nv_bfloat16 ha = __float2bfloat16(a), hb = __float2bfloat16(b);
    ra = a - __bfloat162float(ha);
    rb = b - __bfloat162float(hb);
    __nv_bfloat162 p(ha, hb);
    return *reinterpret_cast<uint32_t*>(&p);
}
__device__ __forceinline__ uint32_t pack_bf16(float a, float b) {
    __nv_bfloat162 p(__float2bfloat16(a), __float2bfloat16(b));
    return *reinterpret_cast<uint32_t*>(&p);
}
// pack P fp32 -> word: low16 = bf16(p), high16 = bf16(p - hi)
__device__ __forceinline__ uint32_t packP(float p) {
    __nv_bfloat16 hi = __float2bfloat16(p);
    __nv_bfloat16 lo = __float2bfloat16(p - __bfloat162float(hi));
    uint16_t hb = *reinterpret_cast<uint16_t*>(&hi);
    uint16_t lb = *reinterpret_cast<uint16_t*>(&lo);
    return (uint32_t)hb | ((uint32_t)lb << 16);
}

// =============================================================================
// Tensor-core (HMMA) GEMM: C[16384,512] = X @ W + bias, bf16 split-3.
// MODE 0: write bf16 hi/lo pair scattered to [b,h,n,d]. MODE 1: fp32 row-major.
// =============================================================================
#define ASTRIDE 40
#define BSTRIDE 136
#define A_BYTES (128*ASTRIDE*2)
#define B_BYTES (32*BSTRIDE*2)
#define OFF_ALO A_BYTES
#define OFF_BHI (2*A_BYTES)
#define OFF_BLO (2*A_BYTES + B_BYTES)
#define GBUF    (2*A_BYTES + 2*B_BYTES)
#define GEMM_SMEM (2*GBUF)

template<int MODE>
__global__ __launch_bounds__(256, 1) void gemm_tc(
    const float* __restrict__ X, const float* __restrict__ W,
    const float* __restrict__ bias, float* __restrict__ out,
    __nv_bfloat16* __restrict__ ohi, __nv_bfloat16* __restrict__ olo)
{
    extern __shared__ char smem[];
    const uint32_t sb = smem_u32(smem);
    const int tid  = threadIdx.x;
    const int wid  = tid >> 5, lane = tid & 31;
    const int wm   = wid >> 2;
    const int wn   = wid & 3;
    const int n0   = blockIdx.x * 128;
    const int m0   = blockIdx.y * 128;

    float acc[4][4][4];
    #pragma unroll
    for (int i = 0; i < 4; i++)
        #pragma unroll
        for (int j = 0; j < 4; j++)
            #pragma unroll
            for (int k = 0; k < 4; k++) acc[i][j][k] = 0.f;

    float4 ra[4], rb[4];

    auto gload = [&](int c) {
        const int k0 = c * 32;
        #pragma unroll
        for (int i = 0; i < 4; i++) {
            int idx = i * 256 + tid;
            int row = idx >> 3, col = (idx & 7) * 4;
            ra[i] = *(const float4*)&X[(size_t)(m0 + row) * 512 + k0 + col];
        }
        #pragma unroll
        for (int i = 0; i < 4; i++) {
            int idx = i * 256 + tid;
            int kk = idx >> 5, col = (idx & 31) * 4;
            rb[i] = *(const float4*)&W[(size_t)(k0 + kk) * 512 + n0 + col];
        }
    };

    auto cstore = [&](int buf) {
        char* bp = smem + buf * GBUF;
        #pragma unroll
        for (int i = 0; i < 4; i++) {
            int idx = i * 256 + tid;
            int row = idx >> 3, col = (idx & 7) * 4;
            float r0, r1, r2, r3;
            uint2 hi, lo;
            hi.x = pack_bf16_res(ra[i].x, ra[i].y, r0, r1);
            hi.y = pack_bf16_res(ra[i].z, ra[i].w, r2, r3);
            lo.x = pack_bf16(r0, r1);
            lo.y = pack_bf16(r2, r3);
            uint32_t off = (uint32_t)(row * ASTRIDE + col) * 2;
            *(uint2*)(bp + off)           = hi;
            *(uint2*)(bp + OFF_ALO + off) = lo;
        }
        #pragma unroll
        for (int i = 0; i < 4; i++) {
            int idx = i * 256 + tid;
            int kk = idx >> 5, col = (idx & 31) * 4;
            float r0, r1, r2, r3;
            uint2 hi, lo;
            hi.x = pack_bf16_res(rb[i].x, rb[i].y, r0, r1);
            hi.y = pack_bf16_res(rb[i].z, rb[i].w, r2, r3);
            lo.x = pack_bf16(r0, r1);
            lo.y = pack_bf16(r2, r3);
            uint32_t off = (uint32_t)(kk * BSTRIDE + col) * 2;
            *(uint2*)(bp + OFF_BHI + off) = hi;
            *(uint2*)(bp + OFF_BLO + off) = lo;
        }
    };

    const uint32_t aLane = (uint32_t)((wm * 64 + (lane & 15)) * ASTRIDE + (lane >> 4) * 8) * 2;
    const uint32_t bLane = (uint32_t)((lane & 15) * BSTRIDE + wn * 32 + (lane >> 4) * 8) * 2;

    auto compute = [&](int buf) {
        const uint32_t base = sb + buf * GBUF;
        #pragma unroll
        for (int ks = 0; ks < 2; ks++) {
            uint32_t ah[4][4], al[4][4], bh[2][4], bl[2][4];
            #pragma unroll
            for (int mt = 0; mt < 4; mt++) {
                uint32_t ad = base + aLane + (uint32_t)(mt * 16 * ASTRIDE + ks * 16) * 2;
                ldsm_x4(ah[mt], ad);
                ldsm_x4(al[mt], ad + OFF_ALO);
            }
            #pragma unroll
            for (int nt = 0; nt < 2; nt++) {
                uint32_t bd = base + OFF_BHI + bLane +
                              (uint32_t)(ks * 16 * BSTRIDE + nt * 16) * 2;
                ldsm_x4t(bh[nt], bd);
                ldsm_x4t(bl[nt], bd + B_BYTES);
            }
            #pragma unroll
            for (int mt = 0; mt < 4; mt++) {
                #pragma unroll
                for (int n8 = 0; n8 < 4; n8++) {
                    const int nt = n8 >> 1, hf = (n8 & 1) * 2;
                    float* c = acc[mt][n8];
                    mma_bf16(c, ah[mt], bh[nt][hf], bh[nt][hf + 1]);
                    mma_bf16(c, ah[mt], bl[nt][hf], bl[nt][hf + 1]);
                    mma_bf16(c, al[mt], bh[nt][hf], bh[nt][hf + 1]);
                }
            }
        }
    };

    gload(0);
    cstore(0);
    __syncthreads();
    for (int c = 0; c < 16; c++) {
        if (c < 15) gload(c + 1);
        compute(c & 1);
        if (c < 15) {
            cstore((c + 1) & 1);
            __syncthreads();
        }
    }

    const int gid = lane >> 2;
    const int cid = (lane & 3) * 2;
    #pragma unroll
    for (int mt = 0; mt < 4; mt++) {
        #pragma unroll
        for (int n8 = 0; n8 < 4; n8++) {
            int row = m0 + wm * 64 + mt * 16 + gid;
            int col = n0 + wn * 32 + n8 * 8 + cid;
            float b0 = __ldg(&bias[col]), b1 = __ldg(&bias[col + 1]);
            float2 v0 = make_float2(acc[mt][n8][0] + b0, acc[mt][n8][1] + b1);
            float2 v1 = make_float2(acc[mt][n8][2] + b0, acc[mt][n8][3] + b1);
            if (MODE == 0) {
                int h = col >> 6, d = col & 63;
                #pragma unroll
                for (int rr = 0; rr < 2; rr++) {
                    int r = row + rr * 8;
                    float2 v = rr ? v1 : v0;
                    int bi = r >> 10, ni = r & 1023;
                    size_t idx = (size_t)(((bi * NH + h) << 10) + ni) * 64 + d;
                    float e0, e1;
                    uint32_t hi = pack_bf16_res(v.x, v.y, e0, e1);
                    uint32_t lo = pack_bf16(e0, e1);
                    *(uint32_t*)&ohi[idx] = hi;
                    *(uint32_t*)&olo[idx] = lo;
                }
            } else {
                *(float2*)&out[(size_t)row * 512 + col]       = v0;
                *(float2*)&out[(size_t)(row + 8) * 512 + col] = v1;
            }
        }
    }
}

// =============================================================================
// Tensor-core fused attention. CTA = (b, h, 32-q-row tile), 8 warps.
//   QK^T via HMMA split-3 (K chunks cp.async double-buffered)
//   softmax w/ scale+log-bias merged, P repacked bf16 hi|lo in-place
//   P@V via HMMA split-3
// =============================================================================
// smem bytes: sS fp32[32][1032] = 132096 | KV 2 bufs x 36864 | Q 9216
#define SSTR 1032
#define ATT_KV0  132096
#define ATT_KVSZ 36864
#define ATT_LO   18432
#define ATT_Q    (ATT_KV0 + 2*ATT_KVSZ)   // 205824
#define ATT_QLO  4608
#define ATT_SMEM (ATT_Q + 9216)           // 215040

__global__ __launch_bounds__(256, 1) void attn_tc(
    const __nv_bfloat16* __restrict__ qhi, const __nv_bfloat16* __restrict__ qlo,
    const __nv_bfloat16* __restrict__ khi, const __nv_bfloat16* __restrict__ klo,
    const __nv_bfloat16* __restrict__ vhi, const __nv_bfloat16* __restrict__ vlo,
    const float* __restrict__ gw, float* __restrict__ mn,
    float* __restrict__ attnout)
{
    extern __shared__ char smem[];
    float* sS = (float*)smem;
    uint32_t* sSw = (uint32_t*)smem;
    const uint32_t sb = smem_u32(smem);

    const int tid = threadIdx.x, wid = tid >> 5, lane = tid & 31;
    const int q0 = blockIdx.x * 32, hh = blockIdx.y, bb = blockIdx.z;
    const size_t bhBase = (size_t)(bb * NH + hh) * NSEQ;

    // ---- stage Q tile (32x64 hi/lo) ----
    {
        int row = tid >> 3, col = (tid & 7) * 8;
        size_t g = (bhBase + q0 + row) * 64 + col;
        *(uint4*)(smem + ATT_Q + row * 144 + col * 2)           = *(const uint4*)&qhi[g];
        *(uint4*)(smem + ATT_Q + ATT_QLO + row * 144 + col * 2) = *(const uint4*)&qlo[g];
    }
    __syncthreads();

    // ---- Q fragments in registers ----
    uint32_t aQh[2][4][4], aQl[2][4][4];
    {
        const uint32_t qaddr = sb + ATT_Q + ((lane & 15) * 72 + (lane >> 4) * 8) * 2;
        #pragma unroll
        for (int mt = 0; mt < 2; mt++)
            #pragma unroll
            for (int ks = 0; ks < 4; ks++) {
                uint32_t a = qaddr + (uint32_t)(mt * 16 * 72 + ks * 16) * 2;
                ldsm_x4(aQh[mt][ks], a);
                ldsm_x4(aQl[mt][ks], a + ATT_QLO);
            }
    }

    // chunk loader (K or V), cp.async 16B x 8 per thread
    auto loadChunk = [&](const __nv_bfloat16* hi, const __nv_bfloat16* lo,
                         int kb, int buf) {
        uint32_t dst = sb + ATT_KV0 + buf * ATT_KVSZ;
        const __nv_bfloat16* sh = hi + (bhBase + kb * 128) * 64;
        const __nv_bfloat16* sl = lo + (bhBase + kb * 128) * 64;
        #pragma unroll
        for (int i = 0; i < 4; i++) {
            int idx = i * 256 + tid;
            int row = idx >> 3, col = (idx & 7) * 8;
            uint32_t d = dst + row * 144 + col * 2;
            cp16(d,          sh + row * 64 + col);
            cp16(d + ATT_LO, sl + row * 64 + col);
        }
        CP_COMMIT();
    };

    // ================= QK^T =================
    const int wslab = wid * 16;
    loadChunk(khi, klo, 0, 0);
    for (int kb = 0; kb < 8; kb++) {
        CP_WAIT0();
        __syncthreads();
        if (kb < 7) loadChunk(khi, klo, kb + 1, (kb + 1) & 1);

        const uint32_t kbase = sb + ATT_KV0 + (kb & 1) * ATT_KVSZ;
        const uint32_t baddr = kbase +
            (uint32_t)((wslab + (lane & 15)) * 72 + (lane >> 4) * 8) * 2;

        float acc[2][2][4];
        #pragma unroll
        for (int i = 0; i < 2; i++)
            #pragma unroll
            for (int j = 0; j < 2; j++)
                #pragma unroll
                for (int k = 0; k < 4; k++) acc[i][j][k] = 0.f;

        #pragma unroll
        for (int ks = 0; ks < 4; ks++) {
            uint32_t bh[4], bl[4];
            ldsm_x4(bh, baddr + ks * 32);
            ldsm_x4(bl, baddr + ks * 32 + ATT_LO);
            #pragma unroll
            for (int mt = 0; mt < 2; mt++) {
                mma_bf16(acc[mt][0], aQh[mt][ks], bh[0], bh[2]);
                mma_bf16(acc[mt][0], aQh[mt][ks], bl[0], bl[2]);
                mma_bf16(acc[mt][0], aQl[mt][ks], bh[0], bh[2]);
                mma_bf16(acc[mt][1], aQh[mt][ks], bh[1], bh[3]);
                mma_bf16(acc[mt][1], aQh[mt][ks], bl[1], bl[3]);
                mma_bf16(acc[mt][1], aQl[mt][ks], bh[1], bh[3]);
            }
        }

        // write raw scores
        int scol = kb * 128 + wslab + (lane & 3) * 2;
        int srow = lane >> 2;
        #pragma unroll
        for (int mt = 0; mt < 2; mt++)
            #pragma unroll
            for (int nt = 0; nt < 2; nt++) {
                *(float2*)&sS[(mt * 16 + srow) * SSTR + scol + nt * 8] =
                    make_float2(acc[mt][nt][0], acc[mt][nt][1]);
                *(float2*)&sS[(mt * 16 + srow + 8) * SSTR + scol + nt * 8] =
                    make_float2(acc[mt][nt][2], acc[mt][nt][3]);
            }
    }
    __syncthreads();

    // ================= softmax (scale + log-bias merged) =================
    {
        #pragma unroll
        for (int rr = 0; rr < 4; rr++) {
            int r = wid + rr * 8;
            float* row = sS + r * SSTR;
            const float* wrow = gw + ((bhBase + q0 + r) << 10);

            float m = -1e30f;
            #pragma unroll
            for (int i = 0; i < 8; i++) {
                int c = (lane + i * 32) * 4;
                float4 f = *(float4*)&row[c];
                float4 w = *(const float4*)&wrow[c];
                f.x = f.x * 0.125f + __logf(fmaxf(w.x, 1e-6f));
                f.y = f.y * 0.125f + __logf(fmaxf(w.y, 1e-6f));
                f.z = f.z * 0.125f + __logf(fmaxf(w.z, 1e-6f));
                f.w = f.w * 0.125f + __logf(fmaxf(w.w, 1e-6f));
                m = fmaxf(m, fmaxf(fmaxf(f.x, f.y), fmaxf(f.z, f.w)));
                *(float4*)&row[c] = f;
            }
            #pragma unroll
            for (int o = 16; o; o >>= 1) m = fmaxf(m, __shfl_xor_sync(0xffffffffu, m, o));

            float sum = 0.f;
            #pragma unroll
            for (int i = 0; i < 8; i++) {
                int c = (lane + i * 32) * 4;
                float4 f = *(float4*)&row[c];
                f.x = __expf(f.x - m); f.y = __expf(f.y - m);
                f.z = __expf(f.z - m); f.w = __expf(f.w - m);
                sum += (f.x + f.y) + (f.z + f.w);
                *(float4*)&row[c] = f;
            }
            #pragma unroll
            for (int o = 16; o; o >>= 1) sum += __shfl_xor_sync(0xffffffffu, sum, o);
            float inv = 1.f / sum;

            float* mrow = mn + ((bhBase + q0 + r) << 10);
            uint32_t* prow = sSw + r * SSTR;
            #pragma unroll
            for (int i = 0; i < 8; i++) {
                int c = (lane + i * 32) * 4;
                float4 f = *(float4*)&row[c];
                f.x *= inv; f.y *= inv; f.z *= inv; f.w *= inv;
                *(float4*)&mrow[c] = f;
                uint4 pk;
                pk.x = packP(f.x); pk.y = packP(f.y);
                pk.z = packP(f.z); pk.w = packP(f.w);
                *(uint4*)&prow[c] = pk;
            }
        }
    }
    __syncthreads();

    // ================= P @ V =================
    const int wm = wid >> 2, wn = wid & 3;
    float accO[2][4];
    #pragma unroll
    for (int i = 0; i < 2; i++)
        #pragma unroll
        for (int j = 0; j < 4; j++) accO[i][j] = 0.f;

    const int g   = lane >> 2;
    const int kc  = (lane & 3) * 2;
    const int pr0 = (wm * 16 + g) * SSTR;
    const int pr1 = (wm * 16 + g + 8) * SSTR;

    loadChunk(vhi, vlo, 0, 0);
    for (int kb = 0; kb < 8; kb++) {
        CP_WAIT0();
        __syncthreads();
        if (kb < 7) loadChunk(vhi, vlo, kb + 1, (kb + 1) & 1);

        const uint32_t vbase = sb + ATT_KV0 + (kb & 1) * ATT_KVSZ;
        const uint32_t vaddr = vbase +
            (uint32_t)((lane & 15) * 72 + wn * 16 + (lane >> 4) * 8) * 2;

        #pragma unroll
        for (int ks = 0; ks < 8; ks++) {
            int kcol = kb * 128 + ks * 16 + kc;
            uint2 u0 = *(uint2*)&sSw[pr0 + kcol];
            uint2 u1 = *(uint2*)&sSw[pr1 + kcol];
            uint2 u2 = *(uint2*)&sSw[pr0 + kcol + 8];
            uint2 u3 = *(uint2*)&sSw[pr1 + kcol + 8];
            uint32_t ah[4], al[4];
            ah[0] = __byte_perm(u0.x, u0.y, 0x5410);
            al[0] = __byte_perm(u0.x, u0.y, 0x7632);
            ah[1] = __byte_perm(u1.x, u1.y, 0x5410);
            al[1] = __byte_perm(u1.x, u1.y, 0x7632);
            ah[2] = __byte_perm(u2.x, u2.y, 0x5410);
            al[2] = __byte_perm(u2.x, u2.y, 0x7632);
            ah[3] = __byte_perm(u3.x, u3.y, 0x5410);
            al[3] = __byte_perm(u3.x, u3.y, 0x7632);

            uint32_t bh[4], bl[4];
            ldsm_x4t(bh, vaddr + (uint32_t)ks * 16 * 144);
            ldsm_x4t(bl, vaddr + (uint32_t)ks * 16 * 144 + ATT_LO);

            mma_bf16(accO[0], ah, bh[0], bh[1]);
            mma_bf16(accO[0], ah, bl[0], bl[1]);
            mma_bf16(accO[0], al, bh[0], bh[1]);
            mma_bf16(accO[1], ah, bh[2], bh[3]);
            mma_bf16(accO[1], ah, bl[2], bl[3]);
            mma_bf16(accO[1], al, bh[2], bh[3]);
        }
    }

    // ---- write O ----
    {
        int orow = q0 + wm * 16 + g;
        int ocol = hh * 64 + wn * 16 + (lane & 3) * 2;
        float* dst = attnout + (size_t)(bb * NSEQ + orow) * 512 + ocol;
        *(float2*)dst             = make_float2(accO[0][0], accO[0][1]);
        *(float2*)(dst + 8 * 512) = make_float2(accO[0][2], accO[0][3]);
        *(float2*)(dst + 8)           = make_float2(accO[1][0], accO[1][1]);
        *(float2*)(dst + 8 * 512 + 8) = make_float2(accO[1][2], accO[1][3]);
    }
}

// =============================================================================
extern "C" void kernel_launch(void* const* d_in, const int* in_sizes, int n_in,
                              void* d_out, int out_size)
{
    const float* queries = (const float*)d_in[0];
    const float* keys    = (const float*)d_in[1];
    const float* values  = (const float*)d_in[2];
    const float* relw    = (const float*)d_in[3];
    const float* Wq = (const float*)d_in[4];
    const float* bq = (const float*)d_in[5];
    const float* Wk = (const float*)d_in[6];
    const float* bk = (const float*)d_in[7];
    const float* Wv = (const float*)d_in[8];
    const float* bv = (const float*)d_in[9];
    const float* Wo = (const float*)d_in[10];
    const float* bo = (const float*)d_in[11];

    float* out_main = (float*)d_out;
    float* out_mn   = (float*)d_out + (size_t)BATCH * NSEQ * DM;

    __nv_bfloat16 *qhi, *qlo, *khi, *klo, *vhi, *vlo;
    float* gattn;
    cudaGetSymbolAddress((void**)&qhi, g_qhi);
    cudaGetSymbolAddress((void**)&qlo, g_qlo);
    cudaGetSymbolAddress((void**)&khi, g_khi);
    cudaGetSymbolAddress((void**)&klo, g_klo);
    cudaGetSymbolAddress((void**)&vhi, g_vhi);
    cudaGetSymbolAddress((void**)&vlo, g_vlo);
    cudaGetSymbolAddress((void**)&gattn, g_attn);

    cudaFuncSetAttribute(gemm_tc<0>, cudaFuncAttributeMaxDynamicSharedMemorySize, GEMM_SMEM);
    cudaFuncSetAttribute(gemm_tc<1>, cudaFuncAttributeMaxDynamicSharedMemorySize, GEMM_SMEM);
    cudaFuncSetAttribute(attn_tc, cudaFuncAttributeMaxDynamicSharedMemorySize, ATT_SMEM);

    dim3 ggrid(4, 128);

    gemm_tc<0><<<ggrid, 256, GEMM_SMEM>>>(queries, Wq, bq, nullptr, qhi, qlo);
    gemm_tc<0><<<ggrid, 256, GEMM_SMEM>>>(keys,    Wk, bk, nullptr, khi, klo);
    gemm_tc<0><<<ggrid, 256, GEMM_SMEM>>>(values,  Wv, bv, nullptr, vhi, vlo);

    attn_tc<<<dim3(32, NH, BATCH), 256, ATT_SMEM>>>(
        qhi, qlo, khi, klo, vhi, vlo, relw, out_mn, gattn);

    gemm_tc<1><<<ggrid, 256, GEMM_SMEM>>>(gattn, Wo, bo, out_main, nullptr, nullptr);
}